// round 8
// baseline (speedup 1.0000x reference)
#include <cuda_runtime.h>
#include <cstdint>

// ---------------- problem constants ----------------
#define D_IN   2048
#define D_H    512
#define BN_EPS 1e-3f

// ---------------- GEMM tiling ----------------
#define BM 128
#define BN 256
#define KC 128                      // k elems (s8) per chunk
#define NCHUNK (D_IN / KC)          // 16
#define B_STAGE (BN * KC)           // 32768
#define SMEM_DYN (3 * B_STAGE)      // 98304

// ---------------- device scratch ----------------
__device__ __align__(16) signed char g_Wq[(size_t)D_H * D_IN];    // [n][k] s8 +-1
__device__ float g_alpha[D_H];
__device__ float g_cbias[D_H];

// ---------------- PTX helpers ----------------
__device__ __forceinline__ uint32_t smem_u32(const void* p) {
    return (uint32_t)__cvta_generic_to_shared(p);
}
__device__ __forceinline__ void cp16(uint32_t s, const void* g) {
    asm volatile("cp.async.cg.shared.global [%0], [%1], 16;" :: "r"(s), "l"(g));
}
__device__ __forceinline__ void cp_commit() {
    asm volatile("cp.async.commit_group;" ::: "memory");
}
template <int N>
__device__ __forceinline__ void cp_wait() {
    asm volatile("cp.async.wait_group %0;" :: "n"(N) : "memory");
}
__device__ __forceinline__ void ldsm4(uint32_t* r, uint32_t addr) {
    asm volatile("ldmatrix.sync.aligned.m8n8.x4.shared.b16 {%0,%1,%2,%3}, [%4];"
                 : "=r"(r[0]), "=r"(r[1]), "=r"(r[2]), "=r"(r[3]) : "r"(addr));
}
__device__ __forceinline__ void mma_s8(int* c, const uint32_t* a,
                                       uint32_t b0, uint32_t b1) {
    asm volatile(
        "mma.sync.aligned.m16n8k32.row.col.s32.s8.s8.s32 "
        "{%0,%1,%2,%3}, {%4,%5,%6,%7}, {%8,%9}, {%0,%1,%2,%3};"
        : "+r"(c[0]), "+r"(c[1]), "+r"(c[2]), "+r"(c[3])
        : "r"(a[0]), "r"(a[1]), "r"(a[2]), "r"(a[3]), "r"(b0), "r"(b1));
}
__device__ __forceinline__ uint32_t prmt(uint32_t a, uint32_t b, uint32_t sel) {
    uint32_t d;
    asm("prmt.b32 %0, %1, %2, %3;" : "=r"(d) : "r"(a), "r"(b), "r"(sel));
    return d;
}
// pack signs of 4 fp32 into 4 s8 (+1 / -1) via PRMT sign-replicate
__device__ __forceinline__ uint32_t pk4(uint4 u) {
    uint32_t s01 = prmt(u.x, u.y, 0x00FBu);
    uint32_t s23 = prmt(u.z, u.w, 0x00FBu);
    return prmt(s01, s23, 0x5410u) | 0x01010101u;
}

// ---------------- prep: W transpose + sign + BN fold ----------------
__global__ __launch_bounds__(256)
void qdbn_prep_kernel(const float* __restrict__ W,
                      const float* __restrict__ b,
                      const float* __restrict__ beta,
                      const float* __restrict__ mean,
                      const float* __restrict__ var) {
    __shared__ signed char tile[32][33];
    const int n0 = blockIdx.x * 32;
    const int k0 = blockIdx.y * 32;
    const int tx = threadIdx.x;   // 32
    const int ty = threadIdx.y;   // 8

    #pragma unroll
    for (int i = 0; i < 32; i += 8) {
        float w = W[(size_t)(k0 + ty + i) * D_H + (n0 + tx)];
        tile[ty + i][tx] = (w >= 0.0f) ? 1 : -1;
    }
    __syncthreads();
    #pragma unroll
    for (int i = 0; i < 32; i += 8) {
        g_Wq[(size_t)(n0 + ty + i) * D_IN + (k0 + tx)] = tile[tx][ty + i];
    }

    if (blockIdx.x == 0 && blockIdx.y == 0) {
        int t = ty * 32 + tx;
        #pragma unroll
        for (int idx = t; idx < D_H; idx += 256) {
            float inv = rsqrtf(var[idx] + BN_EPS);
            g_alpha[idx] = inv;
            g_cbias[idx] = (b[idx] - mean[idx]) * inv + beta[idx];
        }
    }
}

// ---------------- fused GEMM: binarize-X + s8 IMMA + BN ----------------
// CTA 128(M) x 256(N), 512 threads = 16 warps as 4(M) x 4(N) -> warp 32x64.
// A: fp32 X loaded straight into MMA fragments (LDG.128 + prmt pack), NO smem.
//    One k-step-ahead register prefetch (global loads are barrier-free).
// B: s8 from g_Wq via cp.async, 3-stage smem (rows 128B, granule ^ (row&7)).
__global__ __launch_bounds__(512, 1)
void qdbn_fused_kernel(const float* __restrict__ X, float* __restrict__ out) {
    extern __shared__ char dyn_smem[];
    const uint32_t sB0 = smem_u32(dyn_smem);

    const int tid  = threadIdx.x;
    const int wid  = tid >> 5;
    const int lane = tid & 31;
    const int m0 = blockIdx.y * BM;
    const int n0 = blockIdx.x * BN;
    const int wm = (wid >> 2) * 32;   // warp M offset (4 rows of warps)
    const int wn = (wid & 3) * 64;    // warp N offset (4 cols of warps)

    const int g  = lane >> 2;         // fragment row group 0..7
    const int t4 = lane & 3;          // fragment col group

    // B ldmatrix per-lane addressing
    const int t8 = lane >> 3;         // tile id 0..3
    const int rr = lane & 7;          // row within 8x8 tile
    const uint32_t b_row_off = (uint32_t)(wn + (t8 >> 1) * 8 + rr) * KC;
    const uint32_t b_kt = (uint32_t)(t8 & 1);

    // ---- B loader: 4 x cp16 per thread per chunk (512 threads, 2048 granules)
    auto load_B = [&](int stage, int c) {
        const uint32_t bs = sB0 + stage * B_STAGE;
        const size_t kbase = (size_t)c * KC;
        #pragma unroll
        for (int j = 0; j < 4; ++j) {
            int gid = j * 512 + tid;
            int row = gid >> 3;
            int gr  = gid & 7;
            uint32_t dst = bs + row * KC + (uint32_t)((gr ^ (row & 7)) << 4);
            cp16(dst, g_Wq + (size_t)(n0 + row) * D_IN + kbase + gr * 16);
        }
        cp_commit();
    };

    // ---- A fragment loader: chunk c, k-step ks -> a[2][4] packed s8
    // m16n8k32 A layout: reg0 row=g k=t4*4..+3 ; reg1 row=g+8 ; reg2 k+16 ; reg3 both
    const float* xbase = X + (size_t)(m0 + wm + g) * D_IN + t4 * 4;
    auto ldA = [&](int c, int ks, uint32_t a[2][4]) {
        #pragma unroll
        for (int mf = 0; mf < 2; ++mf) {
            const float* p0 = xbase + (size_t)(mf * 16) * D_IN + c * KC + ks * 32;
            a[mf][0] = pk4(*(const uint4*)(p0));
            a[mf][1] = pk4(*(const uint4*)(p0 + (size_t)8 * D_IN));
            a[mf][2] = pk4(*(const uint4*)(p0 + 16));
            a[mf][3] = pk4(*(const uint4*)(p0 + (size_t)8 * D_IN + 16));
        }
    };

    int acc[2][8][4];
    #pragma unroll
    for (int mf = 0; mf < 2; ++mf)
        #pragma unroll
        for (int nf = 0; nf < 8; ++nf)
            #pragma unroll
            for (int q = 0; q < 4; ++q) acc[mf][nf][q] = 0;

    // ---- prologue
    uint32_t acur[2][4], anxt[2][4];
    ldA(0, 0, acur);
    load_B(0, 0);
    load_B(1, 1);

    for (int c = 0; c < NCHUNK; ++c) {
        if (c < NCHUNK - 1) cp_wait<1>();
        else                cp_wait<0>();
        __syncthreads();
        if (c + 2 < NCHUNK) load_B((c + 2) % 3, c + 2);

        const uint32_t b_s = sB0 + (c % 3) * B_STAGE;

        #pragma unroll
        for (int ks = 0; ks < 4; ++ks) {
            // prefetch next A fragments (global; no barrier dependence)
            if (ks < 3)               ldA(c, ks + 1, anxt);
            else if (c + 1 < NCHUNK)  ldA(c + 1, 0, anxt);

            uint32_t bb[4][4];
            #pragma unroll
            for (int np = 0; np < 4; ++np) {
                uint32_t g16 = (uint32_t)(2 * ks) + b_kt;
                ldsm4(bb[np], b_s + b_row_off + np * 16 * KC + ((g16 ^ rr) << 4));
            }
            #pragma unroll
            for (int mf = 0; mf < 2; ++mf)
                #pragma unroll
                for (int np = 0; np < 4; ++np) {
                    mma_s8(acc[mf][2 * np],     acur[mf], bb[np][0], bb[np][1]);
                    mma_s8(acc[mf][2 * np + 1], acur[mf], bb[np][2], bb[np][3]);
                }
            #pragma unroll
            for (int mf = 0; mf < 2; ++mf)
                #pragma unroll
                for (int q = 0; q < 4; ++q) acur[mf][q] = anxt[mf][q];
        }
    }

    // ---- epilogue: BN fold + fp32 store
    const int lr = lane >> 2;
    const int lc = (lane & 3) * 2;
    #pragma unroll
    for (int nf = 0; nf < 8; ++nf) {
        const int cn = n0 + wn + nf * 8 + lc;
        const float al0 = g_alpha[cn],     cb0 = g_cbias[cn];
        const float al1 = g_alpha[cn + 1], cb1 = g_cbias[cn + 1];
        #pragma unroll
        for (int mf = 0; mf < 2; ++mf) {
            const int r0 = m0 + wm + mf * 16 + lr;
            float2 v0, v1;
            v0.x = (float)acc[mf][nf][0] * al0 + cb0;
            v0.y = (float)acc[mf][nf][1] * al1 + cb1;
            v1.x = (float)acc[mf][nf][2] * al0 + cb0;
            v1.y = (float)acc[mf][nf][3] * al1 + cb1;
            *(float2*)(out + (size_t)r0 * D_H + cn) = v0;
            *(float2*)(out + (size_t)(r0 + 8) * D_H + cn) = v1;
        }
    }
}

// ---------------- launch ----------------
extern "C" void kernel_launch(void* const* d_in, const int* in_sizes, int n_in,
                              void* d_out, int out_size) {
    const float* X    = (const float*)d_in[0];
    const float* W    = (const float*)d_in[1];
    const float* b    = (const float*)d_in[2];
    const float* beta = (const float*)d_in[3];
    const float* mean = (const float*)d_in[4];
    const float* var  = (const float*)d_in[5];
    float* out = (float*)d_out;

    const int M = in_sizes[0] / D_IN;   // 32768

    dim3 pb(32, 8);
    dim3 pg(D_H / 32, D_IN / 32);
    qdbn_prep_kernel<<<pg, pb>>>(W, b, beta, mean, var);

    cudaFuncSetAttribute(qdbn_fused_kernel,
                         cudaFuncAttributeMaxDynamicSharedMemorySize, SMEM_DYN);
    dim3 grid(D_H / BN, M / BM);        // (2, 256)
    qdbn_fused_kernel<<<grid, 512, SMEM_DYN>>>(X, out);
}

// round 9
// speedup vs baseline: 1.5981x; 1.5981x over previous
#include <cuda_runtime.h>
#include <cstdint>

// ---------------- problem constants ----------------
#define D_IN   2048
#define D_H    512
#define BN_EPS 1e-3f

// ---------------- GEMM tiling ----------------
#define BM 128
#define BN 256
#define KC 128                      // k elems (s8) per chunk
#define NCHUNK (D_IN / KC)          // 16
#define A_STAGE (BM * KC)           // 16384
#define B_STAGE (BN * KC)           // 32768
#define SMEM_DYN (2 * A_STAGE + 3 * B_STAGE)   // 131072

// ---------------- device scratch ----------------
__device__ __align__(16) signed char g_Wq[(size_t)D_H * D_IN];    // [n][k] s8 +-1
__device__ float g_alpha[D_H];
__device__ float g_cbias[D_H];

// ---------------- PTX helpers ----------------
__device__ __forceinline__ uint32_t smem_u32(const void* p) {
    return (uint32_t)__cvta_generic_to_shared(p);
}
__device__ __forceinline__ void cp16(uint32_t s, const void* g) {
    asm volatile("cp.async.cg.shared.global [%0], [%1], 16;" :: "r"(s), "l"(g));
}
__device__ __forceinline__ void cp_commit() {
    asm volatile("cp.async.commit_group;" ::: "memory");
}
template <int N>
__device__ __forceinline__ void cp_wait() {
    asm volatile("cp.async.wait_group %0;" :: "n"(N) : "memory");
}
__device__ __forceinline__ void sts32(uint32_t addr, uint32_t v) {
    asm volatile("st.shared.b32 [%0], %1;" :: "r"(addr), "r"(v) : "memory");
}
__device__ __forceinline__ void ldsm4(uint32_t* r, uint32_t addr) {
    asm volatile("ldmatrix.sync.aligned.m8n8.x4.shared.b16 {%0,%1,%2,%3}, [%4];"
                 : "=r"(r[0]), "=r"(r[1]), "=r"(r[2]), "=r"(r[3]) : "r"(addr));
}
__device__ __forceinline__ void mma_s8(int* c, const uint32_t* a,
                                       uint32_t b0, uint32_t b1) {
    asm volatile(
        "mma.sync.aligned.m16n8k32.row.col.s32.s8.s8.s32 "
        "{%0,%1,%2,%3}, {%4,%5,%6,%7}, {%8,%9}, {%0,%1,%2,%3};"
        : "+r"(c[0]), "+r"(c[1]), "+r"(c[2]), "+r"(c[3])
        : "r"(a[0]), "r"(a[1]), "r"(a[2]), "r"(a[3]), "r"(b0), "r"(b1));
}
__device__ __forceinline__ uint32_t prmt(uint32_t a, uint32_t b, uint32_t sel) {
    uint32_t d;
    asm("prmt.b32 %0, %1, %2, %3;" : "=r"(d) : "r"(a), "r"(b), "r"(sel));
    return d;
}
// pack signs of 4 fp32 into 4 s8 (+1 / -1) via PRMT sign-replicate
__device__ __forceinline__ uint32_t pk4(uint4 u) {
    uint32_t s01 = prmt(u.x, u.y, 0x00FBu);
    uint32_t s23 = prmt(u.z, u.w, 0x00FBu);
    return prmt(s01, s23, 0x5410u) | 0x01010101u;
}

// ---------------- prep: W transpose + sign + BN fold ----------------
__global__ __launch_bounds__(256)
void qdbn_prep_kernel(const float* __restrict__ W,
                      const float* __restrict__ b,
                      const float* __restrict__ beta,
                      const float* __restrict__ mean,
                      const float* __restrict__ var) {
    __shared__ signed char tile[32][33];
    const int n0 = blockIdx.x * 32;
    const int k0 = blockIdx.y * 32;
    const int tx = threadIdx.x;   // 32
    const int ty = threadIdx.y;   // 8

    #pragma unroll
    for (int i = 0; i < 32; i += 8) {
        float w = W[(size_t)(k0 + ty + i) * D_H + (n0 + tx)];
        tile[ty + i][tx] = (w >= 0.0f) ? 1 : -1;
    }
    __syncthreads();
    #pragma unroll
    for (int i = 0; i < 32; i += 8) {
        g_Wq[(size_t)(n0 + ty + i) * D_IN + (k0 + tx)] = tile[tx][ty + i];
    }

    if (blockIdx.x == 0 && blockIdx.y == 0) {
        int t = ty * 32 + tx;
        #pragma unroll
        for (int idx = t; idx < D_H; idx += 256) {
            float inv = rsqrtf(var[idx] + BN_EPS);
            g_alpha[idx] = inv;
            g_cbias[idx] = (b[idx] - mean[idx]) * inv + beta[idx];
        }
    }
}

// ---------------- fused GEMM: binarize-X + s8 IMMA + BN ----------------
// CTA 128(M) x 256(N), 512 threads = 16 warps as 4(M) x 4(N) -> warp 32x64.
// A: fp32 X via LDG.128 (1 warp = 1 row x 512B, perfect coalescing), prmt
//    sign-pack to s8, STS into 2-stage smem; fragments via ldmatrix.
// B: s8 from g_Wq via cp.async, 3-stage smem.
// smem rows 128B (KC s8), 16B-granule swizzle: g' = g ^ (row & 7).
// Pipeline per iter (proven in R5): cp_wait -> sync -> issue B(c+2) ->
// LDG A(c+1) -> MMA(c) -> STS A(c+1).
__global__ __launch_bounds__(512, 1)
void qdbn_fused_kernel(const float* __restrict__ X, float* __restrict__ out) {
    extern __shared__ char dyn_smem[];
    const uint32_t sA0 = smem_u32(dyn_smem);
    const uint32_t sB0 = sA0 + 2 * A_STAGE;

    const int tid  = threadIdx.x;
    const int wid  = tid >> 5;
    const int lane = tid & 31;
    const int m0 = blockIdx.y * BM;
    const int n0 = blockIdx.x * BN;
    const int wm = (wid >> 2) * 32;   // warp M offset (4 rows of warps)
    const int wn = (wid & 3) * 64;    // warp N offset (4 cols of warps)

    // ldmatrix per-lane addressing
    const int t8 = lane >> 3;         // tile id 0..3
    const int rr = lane & 7;          // row within 8x8 tile
    // A tiles: t -> (m_off = (t&1)*8, k_gran = t>>1)
    const uint32_t a_row_off = (uint32_t)(wm + (t8 & 1) * 8 + rr) * KC;
    const uint32_t a_kt = (uint32_t)(t8 >> 1);
    // B tiles: t -> (n_off = (t>>1)*8, k_gran = t&1)
    const uint32_t b_row_off = (uint32_t)(wn + (t8 >> 1) * 8 + rr) * KC;
    const uint32_t b_kt = (uint32_t)(t8 & 1);

    // ---- B loader: 4 x cp16 per thread per chunk (512 threads, 2048 granules)
    auto load_B = [&](int stage, int c) {
        const uint32_t bs = sB0 + stage * B_STAGE;
        const size_t kbase = (size_t)c * KC;
        #pragma unroll
        for (int j = 0; j < 4; ++j) {
            int gid = j * 512 + tid;
            int row = gid >> 3;
            int gr  = gid & 7;
            uint32_t dst = bs + row * KC + (uint32_t)((gr ^ (row & 7)) << 4);
            cp16(dst, g_Wq + (size_t)(n0 + row) * D_IN + kbase + gr * 16);
        }
        cp_commit();
    };

    // ---- A producer: 8 x (LDG.128 fp32 -> pk4) per chunk, then 8 STS.32
    // thread -> row j*16 + (tid>>5), float4 col = tid&31 (warp = 1 row, 512B)
    const int arow = tid >> 5;        // 0..15
    const int col4 = tid & 31;        // float4 index within row
    uint32_t p[8];
    auto load_A = [&](int c) {
        #pragma unroll
        for (int j = 0; j < 8; ++j) {
            const uint4* src = (const uint4*)(X + (size_t)(m0 + j * 16 + arow) * D_IN
                                              + (size_t)c * KC) + col4;
            p[j] = pk4(__ldg(src));
        }
    };
    auto sts_A = [&](int stage) {
        const uint32_t as = sA0 + stage * A_STAGE;
        const uint32_t g16 = (uint32_t)(col4 >> 2);
        const uint32_t b4  = (uint32_t)((col4 & 3) << 2);
        #pragma unroll
        for (int j = 0; j < 8; ++j) {
            int row = j * 16 + arow;
            sts32(as + row * KC + (((g16 ^ (row & 7)) << 4) | b4), p[j]);
        }
    };

    int acc[2][8][4];
    #pragma unroll
    for (int mf = 0; mf < 2; ++mf)
        #pragma unroll
        for (int nf = 0; nf < 8; ++nf)
            #pragma unroll
            for (int q = 0; q < 4; ++q) acc[mf][nf][q] = 0;

    // ---- prologue: A chunk0 -> smem stage 0; B chunks 0,1 in flight
    load_A(0);
    sts_A(0);
    load_B(0, 0);
    load_B(1, 1);

    for (int c = 0; c < NCHUNK; ++c) {
        if (c < NCHUNK - 1) cp_wait<1>();
        else                cp_wait<0>();
        __syncthreads();                    // closes reads of prior stages

        if (c + 2 < NCHUNK) load_B((c + 2) % 3, c + 2);
        if (c + 1 < NCHUNK) load_A(c + 1);  // LDG into regs, no smem effect

        const uint32_t a_s = sA0 + (c & 1) * A_STAGE;
        const uint32_t b_s = sB0 + (c % 3) * B_STAGE;

        #pragma unroll
        for (int ks = 0; ks < 4; ++ks) {
            uint32_t a[2][4];
            const uint32_t ga = (uint32_t)(2 * ks) + a_kt;
            #pragma unroll
            for (int mf = 0; mf < 2; ++mf)
                ldsm4(a[mf], a_s + a_row_off + mf * 16 * KC + ((ga ^ rr) << 4));
            const uint32_t gb = (uint32_t)(2 * ks) + b_kt;
            #pragma unroll
            for (int np = 0; np < 4; ++np) {
                uint32_t bb[4];
                ldsm4(bb, b_s + b_row_off + np * 16 * KC + ((gb ^ rr) << 4));
                #pragma unroll
                for (int mf = 0; mf < 2; ++mf) {
                    mma_s8(acc[mf][2 * np],     a[mf], bb[0], bb[1]);
                    mma_s8(acc[mf][2 * np + 1], a[mf], bb[2], bb[3]);
                }
            }
        }

        // A stage (c+1)&1 last read at iter c-1, closed by this iter's barrier
        if (c + 1 < NCHUNK) sts_A((c + 1) & 1);
    }

    // ---- epilogue: BN fold + fp32 store
    const int lr = lane >> 2;
    const int lc = (lane & 3) * 2;
    #pragma unroll
    for (int nf = 0; nf < 8; ++nf) {
        const int cn = n0 + wn + nf * 8 + lc;
        const float al0 = g_alpha[cn],     cb0 = g_cbias[cn];
        const float al1 = g_alpha[cn + 1], cb1 = g_cbias[cn + 1];
        #pragma unroll
        for (int mf = 0; mf < 2; ++mf) {
            const int r0 = m0 + wm + mf * 16 + lr;
            float2 v0, v1;
            v0.x = (float)acc[mf][nf][0] * al0 + cb0;
            v0.y = (float)acc[mf][nf][1] * al1 + cb1;
            v1.x = (float)acc[mf][nf][2] * al0 + cb0;
            v1.y = (float)acc[mf][nf][3] * al1 + cb1;
            *(float2*)(out + (size_t)r0 * D_H + cn) = v0;
            *(float2*)(out + (size_t)(r0 + 8) * D_H + cn) = v1;
        }
    }
}

// ---------------- launch ----------------
extern "C" void kernel_launch(void* const* d_in, const int* in_sizes, int n_in,
                              void* d_out, int out_size) {
    const float* X    = (const float*)d_in[0];
    const float* W    = (const float*)d_in[1];
    const float* b    = (const float*)d_in[2];
    const float* beta = (const float*)d_in[3];
    const float* mean = (const float*)d_in[4];
    const float* var  = (const float*)d_in[5];
    float* out = (float*)d_out;

    const int M = in_sizes[0] / D_IN;   // 32768

    dim3 pb(32, 8);
    dim3 pg(D_H / 32, D_IN / 32);
    qdbn_prep_kernel<<<pg, pb>>>(W, b, beta, mean, var);

    cudaFuncSetAttribute(qdbn_fused_kernel,
                         cudaFuncAttributeMaxDynamicSharedMemorySize, SMEM_DYN);
    dim3 grid(D_H / BN, M / BM);        // (2, 256)
    qdbn_fused_kernel<<<grid, 512, SMEM_DYN>>>(X, out);
}

// round 10
// speedup vs baseline: 2.1569x; 1.3497x over previous
#include <cuda_runtime.h>
#include <cstdint>

// ---------------- problem constants ----------------
#define D_IN   2048
#define D_H    512
#define BN_EPS 1e-3f

// ---------------- GEMM tiling ----------------
#define BM 128
#define BN 128
#define KC 128                      // k elems (s8) per chunk
#define NCHUNK (D_IN / KC)          // 16
#define A_STAGE (BM * KC)           // 16384
#define B_STAGE (BN * KC)           // 16384
#define STAGE_BYTES (A_STAGE + B_STAGE)        // 32768
#define SMEM_DYN (3 * STAGE_BYTES)             // 98304 -> 2 CTAs/SM

// ---------------- device scratch ----------------
__device__ __align__(16) signed char g_Xq[(size_t)32768 * D_IN];  // 64 MB
__device__ __align__(16) signed char g_Wq[(size_t)D_H * D_IN];    // 1 MB, [n][k]
__device__ float g_alpha[D_H];
__device__ float g_cbias[D_H];

// ---------------- PTX helpers ----------------
__device__ __forceinline__ uint32_t smem_u32(const void* p) {
    return (uint32_t)__cvta_generic_to_shared(p);
}
__device__ __forceinline__ void cp16(uint32_t s, const void* g) {
    asm volatile("cp.async.cg.shared.global [%0], [%1], 16;" :: "r"(s), "l"(g));
}
__device__ __forceinline__ void cp_commit() {
    asm volatile("cp.async.commit_group;" ::: "memory");
}
template <int N>
__device__ __forceinline__ void cp_wait() {
    asm volatile("cp.async.wait_group %0;" :: "n"(N) : "memory");
}
__device__ __forceinline__ void ldsm4(uint32_t* r, uint32_t addr) {
    asm volatile("ldmatrix.sync.aligned.m8n8.x4.shared.b16 {%0,%1,%2,%3}, [%4];"
                 : "=r"(r[0]), "=r"(r[1]), "=r"(r[2]), "=r"(r[3]) : "r"(addr));
}
__device__ __forceinline__ void mma_s8(int* c, const uint32_t* a,
                                       uint32_t b0, uint32_t b1) {
    asm volatile(
        "mma.sync.aligned.m16n8k32.row.col.s32.s8.s8.s32 "
        "{%0,%1,%2,%3}, {%4,%5,%6,%7}, {%8,%9}, {%0,%1,%2,%3};"
        : "+r"(c[0]), "+r"(c[1]), "+r"(c[2]), "+r"(c[3])
        : "r"(a[0]), "r"(a[1]), "r"(a[2]), "r"(a[3]), "r"(b0), "r"(b1));
}
__device__ __forceinline__ uint32_t prmt(uint32_t a, uint32_t b, uint32_t sel) {
    uint32_t d;
    asm("prmt.b32 %0, %1, %2, %3;" : "=r"(d) : "r"(a), "r"(b), "r"(sel));
    return d;
}
// pack signs of 4 fp32 into 4 s8 (+1 / -1) via PRMT sign-replicate
__device__ __forceinline__ uint32_t pk4(uint4 u) {
    uint32_t s01 = prmt(u.x, u.y, 0x00FBu);
    uint32_t s23 = prmt(u.z, u.w, 0x00FBu);
    return prmt(s01, s23, 0x5410u) | 0x01010101u;
}

// ---------------- prep: W transpose + sign + BN fold ----------------
__global__ __launch_bounds__(256)
void qdbn_prep_kernel(const float* __restrict__ W,
                      const float* __restrict__ b,
                      const float* __restrict__ beta,
                      const float* __restrict__ mean,
                      const float* __restrict__ var) {
    __shared__ signed char tile[32][33];
    const int n0 = blockIdx.x * 32;
    const int k0 = blockIdx.y * 32;
    const int tx = threadIdx.x;   // 32
    const int ty = threadIdx.y;   // 8

    #pragma unroll
    for (int i = 0; i < 32; i += 8) {
        float w = W[(size_t)(k0 + ty + i) * D_H + (n0 + tx)];
        tile[ty + i][tx] = (w >= 0.0f) ? 1 : -1;
    }
    __syncthreads();
    #pragma unroll
    for (int i = 0; i < 32; i += 8) {
        g_Wq[(size_t)(n0 + ty + i) * D_IN + (k0 + tx)] = tile[tx][ty + i];
    }

    if (blockIdx.x == 0 && blockIdx.y == 0) {
        int t = ty * 32 + tx;
        #pragma unroll
        for (int idx = t; idx < D_H; idx += 256) {
            float inv = rsqrtf(var[idx] + BN_EPS);
            g_alpha[idx] = inv;
            g_cbias[idx] = (b[idx] - mean[idx]) * inv + beta[idx];
        }
    }
}

// ---------------- pass 1: binarize X fp32 -> s8 (streaming) ----------------
__global__ __launch_bounds__(256)
void qdbn_binarize_kernel(const float4* __restrict__ X) {
    uint4* xq = reinterpret_cast<uint4*>(g_Xq);
    uint32_t i = blockIdx.x * 256u + threadIdx.x;   // one uint4 (16 s8) per thread
    const float4* p = X + (size_t)i * 4;
    uint4 o;
    o.x = pk4(*(const uint4*)(p + 0));
    o.y = pk4(*(const uint4*)(p + 1));
    o.z = pk4(*(const uint4*)(p + 2));
    o.w = pk4(*(const uint4*)(p + 3));
    xq[i] = o;
}

// ---------------- GEMM: s8 IMMA, both operands via cp.async ----------------
// CTA 128(M) x 128(N), 256 threads = 8 warps as 4(M) x 2(N) -> warp 32x64.
// 96KB smem (3 stages x (A 16KB + B 16KB)) -> 2 CTAs/SM; regs capped at 128.
// smem rows 128B (KC s8), 16B-granule swizzle: g' = g ^ (row & 7).
__global__ __launch_bounds__(256, 2)
void qdbn_imma_kernel(float* __restrict__ out) {
    extern __shared__ char dyn_smem[];
    const uint32_t base = smem_u32(dyn_smem);

    const int tid  = threadIdx.x;
    const int wid  = tid >> 5;
    const int lane = tid & 31;
    const int m0 = blockIdx.y * BM;
    const int n0 = blockIdx.x * BN;
    const int wm = (wid >> 1) * 32;   // warp M offset (4 rows of warps)
    const int wn = (wid & 1) * 64;    // warp N offset (2 cols of warps)

    // ldmatrix per-lane addressing (identical mapping proven in R9)
    const int t8 = lane >> 3;         // tile id 0..3
    const int rr = lane & 7;          // row within 8x8 tile
    const uint32_t a_row_off = (uint32_t)(wm + (t8 & 1) * 8 + rr) * KC;
    const uint32_t a_kt = (uint32_t)(t8 >> 1);
    const uint32_t b_row_off = (uint32_t)(wn + (t8 >> 1) * 8 + rr) * KC;
    const uint32_t b_kt = (uint32_t)(t8 & 1);

    // ---- loader: A 4 x cp16 + B 4 x cp16 per thread per chunk
    auto load_chunk = [&](int stage, int c) {
        const uint32_t as = base + stage * STAGE_BYTES;
        const uint32_t bs = as + A_STAGE;
        const size_t kbase = (size_t)c * KC;
        #pragma unroll
        for (int j = 0; j < 4; ++j) {
            int gid = j * 256 + tid;          // 0..1023
            int row = gid >> 3;
            int gr  = gid & 7;
            uint32_t sw = (uint32_t)((gr ^ (row & 7)) << 4);
            cp16(as + row * KC + sw,
                 g_Xq + (size_t)(m0 + row) * D_IN + kbase + gr * 16);
        }
        #pragma unroll
        for (int j = 0; j < 4; ++j) {
            int gid = j * 256 + tid;
            int row = gid >> 3;
            int gr  = gid & 7;
            uint32_t sw = (uint32_t)((gr ^ (row & 7)) << 4);
            cp16(bs + row * KC + sw,
                 g_Wq + (size_t)(n0 + row) * D_IN + kbase + gr * 16);
        }
        cp_commit();
    };

    int acc[2][8][4];
    #pragma unroll
    for (int mf = 0; mf < 2; ++mf)
        #pragma unroll
        for (int nf = 0; nf < 8; ++nf)
            #pragma unroll
            for (int q = 0; q < 4; ++q) acc[mf][nf][q] = 0;

    // ---- prologue: chunks 0,1 in flight
    load_chunk(0, 0);
    load_chunk(1, 1);

    for (int c = 0; c < NCHUNK; ++c) {
        if (c < NCHUNK - 1) cp_wait<1>();   // chunk c complete
        else                cp_wait<0>();
        __syncthreads();                    // closes reads of stage (c+2)%3 from iter c-1

        if (c + 2 < NCHUNK) load_chunk((c + 2) % 3, c + 2);

        const uint32_t a_s = base + (c % 3) * STAGE_BYTES;
        const uint32_t b_s = a_s + A_STAGE;

        #pragma unroll
        for (int ks = 0; ks < 4; ++ks) {
            uint32_t a[2][4];
            const uint32_t ga = (uint32_t)(2 * ks) + a_kt;
            #pragma unroll
            for (int mf = 0; mf < 2; ++mf)
                ldsm4(a[mf], a_s + a_row_off + mf * 16 * KC + ((ga ^ rr) << 4));
            const uint32_t gb = (uint32_t)(2 * ks) + b_kt;
            #pragma unroll
            for (int np = 0; np < 4; ++np) {
                uint32_t bb[4];
                ldsm4(bb, b_s + b_row_off + np * 16 * KC + ((gb ^ rr) << 4));
                #pragma unroll
                for (int mf = 0; mf < 2; ++mf) {
                    mma_s8(acc[mf][2 * np],     a[mf], bb[0], bb[1]);
                    mma_s8(acc[mf][2 * np + 1], a[mf], bb[2], bb[3]);
                }
            }
        }
    }

    // ---- epilogue: BN fold + fp32 store
    const int lr = lane >> 2;
    const int lc = (lane & 3) * 2;
    #pragma unroll
    for (int nf = 0; nf < 8; ++nf) {
        const int cn = n0 + wn + nf * 8 + lc;
        const float al0 = g_alpha[cn],     cb0 = g_cbias[cn];
        const float al1 = g_alpha[cn + 1], cb1 = g_cbias[cn + 1];
        #pragma unroll
        for (int mf = 0; mf < 2; ++mf) {
            const int r0 = m0 + wm + mf * 16 + lr;
            float2 v0, v1;
            v0.x = (float)acc[mf][nf][0] * al0 + cb0;
            v0.y = (float)acc[mf][nf][1] * al1 + cb1;
            v1.x = (float)acc[mf][nf][2] * al0 + cb0;
            v1.y = (float)acc[mf][nf][3] * al1 + cb1;
            *(float2*)(out + (size_t)r0 * D_H + cn) = v0;
            *(float2*)(out + (size_t)(r0 + 8) * D_H + cn) = v1;
        }
    }
}

// ---------------- launch ----------------
extern "C" void kernel_launch(void* const* d_in, const int* in_sizes, int n_in,
                              void* d_out, int out_size) {
    const float* X    = (const float*)d_in[0];
    const float* W    = (const float*)d_in[1];
    const float* b    = (const float*)d_in[2];
    const float* beta = (const float*)d_in[3];
    const float* mean = (const float*)d_in[4];
    const float* var  = (const float*)d_in[5];
    float* out = (float*)d_out;

    const int M = in_sizes[0] / D_IN;   // 32768

    dim3 pb(32, 8);
    dim3 pg(D_H / 32, D_IN / 32);
    qdbn_prep_kernel<<<pg, pb>>>(W, b, beta, mean, var);

    const int nthreads16 = (M * D_IN) / 16;
    qdbn_binarize_kernel<<<nthreads16 / 256, 256>>>((const float4*)X);

    cudaFuncSetAttribute(qdbn_imma_kernel,
                         cudaFuncAttributeMaxDynamicSharedMemorySize, SMEM_DYN);
    dim3 grid(D_H / BN, M / BM);        // (4, 256)
    qdbn_imma_kernel<<<grid, 256, SMEM_DYN>>>(out);
}